// round 11
// baseline (speedup 1.0000x reference)
#include <cuda_runtime.h>

#define Bq 32
#define Tq 512
#define Dq 128
#define Nq 1024
#define NOISE_C 0.001f
#define GRID_G 128
#define NCOL 8
#define NTHR 512
#define NW 16          // warps per CTA
#define NGRP 16        // producer groups / chunks
#define ARRV 128       // arrivals per group counter per step (16 warps x 8 CTAs)

// States double buffer, duplicated-packed: g_Sd[ph][k2][b] = (s_{2k2},s_{2k2},s_{2k2+1},s_{2k2+1})
// -> a ulonglong2 load yields two ready f32x2 operands (no MOV packing).
__device__ float4 g_Sd[2][Nq / 2][Bq];
// 16 group counters, one 128B line each. Group g = CTAs [8g,8g+8) = k chunk [64g,64g+64).
// Monotonic; reset by init_kernel each launch -> replay-safe.
__device__ unsigned g_gcnt[NGRP * 32];

// out[:,0,:] = step0 ; pack states0 (duplicated) into g_Sd[0] ; reset counters
__global__ void init_kernel(const float* __restrict__ states0,
                            const float* __restrict__ step0,
                            float* __restrict__ out) {
    int i = blockIdx.x * blockDim.x + threadIdx.x;  // 0 .. 32767
    int b = i >> 10;
    int n = i & 1023;
    out[(size_t)b * Tq * Nq + n] = step0[i];
    float v = states0[i];
    ((float2*)&g_Sd[0][n >> 1][b])[n & 1] = make_float2(v, v);
    if (i < NGRP * 32) g_gcnt[i] = 0u;
}

// xin GEMM (R9 winner, unchanged): out[b,t,n] = scale * sum_d x[b,t,d]*w_input[d,n], t in [1,512)
__global__ __launch_bounds__(512) void xin_gemm(const float* __restrict__ x,
                                                const float* __restrict__ w_in,
                                                const float* __restrict__ scale_p,
                                                float* __restrict__ out) {
    __shared__ float xs[128][33];
    __shared__ __align__(16) float ws[32][132];
    __shared__ int rowoff[128];

    const int tid = threadIdx.x;
    const int tx = tid & 15;
    const int ty = tid >> 4;
    const int bn = blockIdx.x;
    const int bm = blockIdx.y;
    const float sc = *scale_p;

    if (tid < 128) {
        int m = bm * 128 + tid;
        if (m < Bq * (Tq - 1)) {
            int b = m / (Tq - 1);
            int t = m - b * (Tq - 1) + 1;
            rowoff[tid] = (b * Tq + t) * Dq;
        } else {
            rowoff[tid] = -1;
        }
    }

    unsigned long long acc[4][4];
#pragma unroll
    for (int i = 0; i < 4; ++i)
#pragma unroll
        for (int j = 0; j < 4; ++j) acc[i][j] = 0ull;

    __syncthreads();

    for (int kc = 0; kc < 4; ++kc) {
#pragma unroll
        for (int l = 0; l < 8; ++l) {
            int idx = tid + l * 512;
            int r = idx >> 5, k = idx & 31;
            int ro = rowoff[r];
            xs[r][k] = (ro >= 0) ? x[(size_t)ro + kc * 32 + k] : 0.f;
        }
#pragma unroll
        for (int l = 0; l < 8; ++l) {
            int idx = tid + l * 512;
            int kk = idx >> 7, c = idx & 127;
            ws[kk][c] = w_in[(size_t)(kc * 32 + kk) * Nq + bn * 128 + c];
        }
        __syncthreads();

#pragma unroll
        for (int k = 0; k < 32; ++k) {
            float xr[4];
#pragma unroll
            for (int i = 0; i < 4; ++i) xr[i] = xs[ty * 4 + i][k];
            const ulonglong2* wsp = (const ulonglong2*)&ws[k][tx * 8];
            ulonglong2 w0 = wsp[0];
            ulonglong2 w1 = wsp[1];
#pragma unroll
            for (int i = 0; i < 4; ++i) {
                unsigned xb = __float_as_uint(xr[i]);
                unsigned long long xv;
                asm("mov.b64 %0, {%1, %1};" : "=l"(xv) : "r"(xb));
                asm("fma.rn.f32x2 %0, %1, %2, %0;" : "+l"(acc[i][0]) : "l"(xv), "l"(w0.x));
                asm("fma.rn.f32x2 %0, %1, %2, %0;" : "+l"(acc[i][1]) : "l"(xv), "l"(w0.y));
                asm("fma.rn.f32x2 %0, %1, %2, %0;" : "+l"(acc[i][2]) : "l"(xv), "l"(w1.x));
                asm("fma.rn.f32x2 %0, %1, %2, %0;" : "+l"(acc[i][3]) : "l"(xv), "l"(w1.y));
            }
        }
        __syncthreads();
    }

#pragma unroll
    for (int i = 0; i < 4; ++i) {
        int ro = rowoff[ty * 4 + i];
        if (ro < 0) continue;
        float4* op = (float4*)(out + (size_t)(ro >> 7) * Nq + bn * 128 + tx * 8);
        float4 v0, v1;
        v0.x = __uint_as_float((unsigned)acc[i][0]) * sc;
        v0.y = __uint_as_float((unsigned)(acc[i][0] >> 32)) * sc;
        v0.z = __uint_as_float((unsigned)acc[i][1]) * sc;
        v0.w = __uint_as_float((unsigned)(acc[i][1] >> 32)) * sc;
        v1.x = __uint_as_float((unsigned)acc[i][2]) * sc;
        v1.y = __uint_as_float((unsigned)(acc[i][2] >> 32)) * sc;
        v1.z = __uint_as_float((unsigned)acc[i][3]) * sc;
        v1.w = __uint_as_float((unsigned)(acc[i][3] >> 32)) * sc;
        op[0] = v0;
        op[1] = v1;
    }
}

struct RecurSmem {
    float Wsm[Nq][NCOL];        // 32 KB
    float red[2][NW][Bq][9];    // 36 KB, parity double-buffered
};
#define RECUR_SMEM_BYTES ((int)sizeof(RecurSmem))

// Persistent recurrence. 128 CTAs x 512 thr. Per-warp dataflow gating (R8 winner)
// + duplicated-state operands (no MOV packing) + per-warp epilogue & arrival with
// parity-double-buffered reduction (single __syncthreads per step).
__global__ __launch_bounds__(NTHR, 1) void recur_kernel(const float* __restrict__ w_res,
                                                        const float* __restrict__ noise,
                                                        float* __restrict__ out) {
    extern __shared__ RecurSmem sm[];

    const int tid = threadIdx.x;
    const int cta = blockIdx.x;
    const int col0 = cta * NCOL;
    unsigned* own_cnt = &g_gcnt[(cta >> 3) * 32];   // our group's counter

    for (int i = tid; i < Nq * NCOL; i += NTHR) {
        int k = i >> 3, c = i & 7;
        sm->Wsm[k][c] = w_res[(size_t)k * Nq + col0 + c];
    }
    __syncthreads();

    const int warp = tid >> 5;
    const int lane = tid & 31;  // = batch b for the K-reduction
    unsigned* my_chunk_cnt = &g_gcnt[warp * 32];    // counter gating THIS warp's k chunk

    // per-warp epilogue: lanes 0..15 handle element e = warp*16 + lane
    const bool epi = (lane < 16);
    const int e = warp * 16 + lane;
    const int eb = (e >> 3) & 31;
    const int ec = e & 7;
    const int en = col0 + ec;
    const float nz = NOISE_C * noise[eb * Nq + en];   // uniform; epi lanes use it
    float* outp = out + (size_t)eb * Tq * Nq + en;
    float2* sD0 = ((float2*)&g_Sd[0][en >> 1][eb]) + (en & 1);
    float2* sD1 = ((float2*)&g_Sd[1][en >> 1][eb]) + (en & 1);

    const ulonglong2* Wp0 = (const ulonglong2*)&sm->Wsm[warp * 64][0];

    for (int t = 1; t < Tq; ++t) {
        const int p = t & 1;
        // warp's k2 range: [32*warp, 32*warp+32) ; each float4 = 2 dup'd k values
        const float4* Sp = &g_Sd[(t - 1) & 1][warp * 32][lane];

        float xin = epi ? outp[(size_t)t * Nq] : 0.f;  // own data; gate-independent

        // ---- per-warp gate: wait for OUR chunk's producers (prev step) ----
        const unsigned tgt = (unsigned)ARRV * (unsigned)(t - 1);
        if (lane == 0) {
            unsigned v;
            do {
                asm volatile("ld.acquire.gpu.u32 %0, [%1];"
                             : "=r"(v) : "l"(my_chunk_cnt) : "memory");
                if (v < tgt) __nanosleep(8);
            } while (v < tgt);
        }
        __syncwarp();

        unsigned long long a0 = 0, a1 = 0, a2 = 0, a3 = 0;
        const ulonglong2* wp = Wp0;

        // depth-8 rolling prefetch over 32 float4 loads (each = 2 dup'd k)
        float4 buf[8];
#pragma unroll
        for (int j = 0; j < 8; ++j) buf[j] = __ldcg(Sp + j * Bq);

#pragma unroll
        for (int it = 0; it < 32; ++it) {
            float4 s = buf[it & 7];
            if (it < 24) buf[it & 7] = __ldcg(Sp + (it + 8) * Bq);
            unsigned long long sv0 = ((const unsigned long long*)&s)[0];  // dup k
            unsigned long long sv1 = ((const unsigned long long*)&s)[1];  // dup k+1
            ulonglong2 u0 = wp[0];
            ulonglong2 u1 = wp[1];
            ulonglong2 u2 = wp[2];
            ulonglong2 u3 = wp[3];
            wp += 4;
            asm("fma.rn.f32x2 %0, %1, %2, %0;" : "+l"(a0) : "l"(sv0), "l"(u0.x));
            asm("fma.rn.f32x2 %0, %1, %2, %0;" : "+l"(a1) : "l"(sv0), "l"(u0.y));
            asm("fma.rn.f32x2 %0, %1, %2, %0;" : "+l"(a2) : "l"(sv0), "l"(u1.x));
            asm("fma.rn.f32x2 %0, %1, %2, %0;" : "+l"(a3) : "l"(sv0), "l"(u1.y));
            asm("fma.rn.f32x2 %0, %1, %2, %0;" : "+l"(a0) : "l"(sv1), "l"(u2.x));
            asm("fma.rn.f32x2 %0, %1, %2, %0;" : "+l"(a1) : "l"(sv1), "l"(u2.y));
            asm("fma.rn.f32x2 %0, %1, %2, %0;" : "+l"(a2) : "l"(sv1), "l"(u3.x));
            asm("fma.rn.f32x2 %0, %1, %2, %0;" : "+l"(a3) : "l"(sv1), "l"(u3.y));
        }

        float (*rp)[Bq][9] = sm->red[p];
        rp[warp][lane][0] = __uint_as_float((unsigned)a0);
        rp[warp][lane][1] = __uint_as_float((unsigned)(a0 >> 32));
        rp[warp][lane][2] = __uint_as_float((unsigned)a1);
        rp[warp][lane][3] = __uint_as_float((unsigned)(a1 >> 32));
        rp[warp][lane][4] = __uint_as_float((unsigned)a2);
        rp[warp][lane][5] = __uint_as_float((unsigned)(a2 >> 32));
        rp[warp][lane][6] = __uint_as_float((unsigned)a3);
        rp[warp][lane][7] = __uint_as_float((unsigned)(a3 >> 32));
        __syncthreads();   // single CTA-wide sync per step (red[p] complete)

        if (epi) {
            float sum = 0.f;
#pragma unroll
            for (int w = 0; w < NW; ++w) sum += rp[w][eb][ec];

            float post = tanhf(sum + xin) + nz;
            outp[(size_t)t * Nq] = post;              // own element — safe
            float2 d = make_float2(post, post);       // duplicated state publish
            *((p) ? sD1 : sD0) = d;
        }
        // per-warp arrival: epi lanes' stores ordered by syncwarp, published by
        // lane 0's release. Fast warps proceed into step t+1 immediately.
        __syncwarp();
        if (lane == 0) {
            asm volatile("red.release.gpu.add.u32 [%0], %1;"
                         :: "l"(own_cnt), "r"(1u) : "memory");
        }
    }
}

extern "C" void kernel_launch(void* const* d_in, const int* in_sizes, int n_in,
                              void* d_out, int out_size) {
    (void)in_sizes; (void)n_in; (void)out_size;
    const float* x       = (const float*)d_in[0];
    const float* w_input = (const float*)d_in[1];
    const float* w_res   = (const float*)d_in[2];
    const float* w_scale = (const float*)d_in[3];
    const float* states0 = (const float*)d_in[4];
    const float* step0   = (const float*)d_in[5];
    const float* rnoise  = (const float*)d_in[6];
    float* out = (float*)d_out;

    cudaFuncSetAttribute(recur_kernel, cudaFuncAttributeMaxDynamicSharedMemorySize,
                         RECUR_SMEM_BYTES);

    // order: xin, init, recur (keeps ncu -s 5 on a real kernel)
    dim3 g(8, 128);
    xin_gemm<<<g, 512>>>(x, w_input, w_scale, out);
    init_kernel<<<128, 256>>>(states0, step0, out);
    recur_kernel<<<GRID_G, NTHR, RECUR_SMEM_BYTES>>>(w_res, rnoise, out);
}

// round 12
// speedup vs baseline: 1.3056x; 1.3056x over previous
#include <cuda_runtime.h>

#define Bq 32
#define Tq 512
#define Dq 128
#define Nq 1024
#define NOISE_C 0.001f
#define GRID_G 128
#define NCOL 8
#define NTHR 512
#define NW 16          // warps per CTA
#define KSL 64         // k per warp (= one chunk)
#define ITS 16         // float4 iterations per warp
#define NGRP 16        // producer groups / chunks
#define GSZ 8          // CTAs per group

typedef unsigned long long ull;

// States double buffer, k-blocked transposed: g_S4[phase][k/4][b] = float4 of S[b][4k..4k+3]
__device__ float4 g_S4[2][Nq / 4][Bq];
// 16 group counters, one 128B line each. Group g = CTAs [8g,8g+8) = k chunk [64g,64g+64).
// Monotonic; reset by init_kernel each launch -> replay-safe.
__device__ unsigned g_gcnt[NGRP * 32];

// out[:,0,:] = step0 ; pack states0 into g_S4[0] ; reset counters
__global__ void init_kernel(const float* __restrict__ states0,
                            const float* __restrict__ step0,
                            float* __restrict__ out) {
    int i = blockIdx.x * blockDim.x + threadIdx.x;  // 0 .. 32767
    int b = i >> 10;
    int n = i & 1023;
    out[(size_t)b * Tq * Nq + n] = step0[i];
    ((float*)&g_S4[0][n >> 2][b])[n & 3] = states0[i];
    if (i < NGRP * 32) g_gcnt[i] = 0u;
}

struct RecurSmem {
    float Wsm[Nq][NCOL];       // 32 KB  reservoir slice
    float red[NW][Bq][9];      // 18 KB  K-reduction partials
    float xs_x[2][Bq][132];    // 33.8 KB  x tile, parity double-buffered
    float wt[NCOL][132];       // 4.2 KB  w_input slice (pre-scaled, transposed)
    float xr2[2][256];         // 2 KB  xin half-dot partials
};
#define RECUR_SMEM_BYTES ((int)sizeof(RecurSmem))

// Persistent recurrence with FUSED input projection. 128 CTAs x 512 threads.
// R9-proven core: per-warp dataflow gating, fp32x2 FMA, full-chunk prefetch,
// two syncthreads/step, 1 arrival per CTA per step.
// New: xin computed in-kernel. x[:,t+1,:] staged to SMEM during step t (synced by
// sync1); half-dots for step t computed at loop top (gate-independent -> fills
// the gate-wait slack); epilogue sums two halves. xin_gemm kernel deleted.
__global__ __launch_bounds__(NTHR, 1) void recur_kernel(const float* __restrict__ w_res,
                                                        const float* __restrict__ x,
                                                        const float* __restrict__ w_in,
                                                        const float* __restrict__ scale_p,
                                                        const float* __restrict__ noise,
                                                        float* __restrict__ out) {
    extern __shared__ RecurSmem sm[];
    const float4* x4 = (const float4*)x;

    const int tid = threadIdx.x;
    const int cta = blockIdx.x;
    const int col0 = cta * NCOL;
    unsigned* own_cnt = &g_gcnt[(cta >> 3) * 32];   // our group's counter

    for (int i = tid; i < Nq * NCOL; i += NTHR) {
        int k = i >> 3, c = i & 7;
        sm->Wsm[k][c] = w_res[(size_t)k * Nq + col0 + c];
    }
    // w_input slice, transposed + pre-scaled: wt[c][d] = w_in[d][col0+c] * scale
    const float sc = *scale_p;
    for (int i = tid; i < Dq * NCOL; i += NTHR) {
        int d = i >> 3, c = i & 7;
        sm->wt[c][d] = w_in[(size_t)d * Nq + col0 + c] * sc;
    }
    // stage x(:, t=1, :) into parity buffer 1
    {
#pragma unroll
        for (int l = 0; l < 2; ++l) {
            int idx = tid + l * 512;            // 0..1023
            int b = idx >> 5, d4 = idx & 31;
            float4 v = x4[((size_t)b * Tq + 1) * 32 + d4];
            *(float4*)&sm->xs_x[1][b][d4 * 4] = v;
        }
    }
    __syncthreads();

    const int warp = tid >> 5;
    const int lane = tid & 31;  // = batch b for the K-reduction
    unsigned* my_chunk_cnt = &g_gcnt[warp * 32];    // counter gating THIS warp's k chunk

    // epilogue mapping (first 256 threads): thread -> (eb, ec)
    const bool epi = (tid < Bq * NCOL);
    const int eb = (tid >> 3) & 31;
    const int ec = tid & 7;
    const int en = col0 + ec;
    const float nz = epi ? NOISE_C * noise[eb * Nq + en] : 0.f;
    float* outp = out + (size_t)eb * Tq * Nq + en;
    float* sW0 = &((float*)&g_S4[0][en >> 2][eb])[en & 3];
    float* sW1 = &((float*)&g_S4[1][en >> 2][eb])[en & 3];

    // fused-xin half-dot mapping: all 512 threads, element he = tid&255, half hh
    const int he = tid & 255;
    const int hh = tid >> 8;
    const int heb = (he >> 3) & 31;
    const int hec = he & 7;

    const ulonglong2* Wp0 = (const ulonglong2*)&sm->Wsm[warp * KSL][0];

    for (int t = 1; t < Tq; ++t) {
        const int p = t & 1;

        // ---- fused xin: half-dot over d in [64*hh, 64*hh+64) (gate-independent) ----
        {
            const float4* xp = (const float4*)&sm->xs_x[p][heb][hh * 64];
            const float4* wp4 = (const float4*)&sm->wt[hec][hh * 64];
            ull acc2 = 0;
#pragma unroll
            for (int j = 0; j < 16; ++j) {
                float4 xv = xp[j];
                float4 wv = wp4[j];
                ull x01 = ((const ull*)&xv)[0], x23 = ((const ull*)&xv)[1];
                ull w01 = ((const ull*)&wv)[0], w23 = ((const ull*)&wv)[1];
                asm("fma.rn.f32x2 %0, %1, %2, %0;" : "+l"(acc2) : "l"(x01), "l"(w01));
                asm("fma.rn.f32x2 %0, %1, %2, %0;" : "+l"(acc2) : "l"(x23), "l"(w23));
            }
            sm->xr2[hh][he] = __uint_as_float((unsigned)acc2) +
                              __uint_as_float((unsigned)(acc2 >> 32));
        }

        // ---- per-warp gate: wait for OUR chunk's producers (prev step) ----
        const unsigned tgt = (unsigned)GSZ * (unsigned)(t - 1);
        if (lane == 0) {
            unsigned v;
            do {
                asm volatile("ld.acquire.gpu.u32 %0, [%1];"
                             : "=r"(v) : "l"(my_chunk_cnt) : "memory");
                if (v < tgt) __nanosleep(8);
            } while (v < tgt);
        }
        __syncwarp();

        // ---- main FMA (R9 exact): full-chunk prefetch, MOV-dup, fp32x2 ----
        const float4* Sp = ((const float4*)g_S4[(t - 1) & 1]) + warp * (ITS * Bq) + lane;
        float4 buf[ITS];
#pragma unroll
        for (int j = 0; j < ITS; ++j) buf[j] = __ldcg(Sp + j * Bq);

        unsigned long long a0 = 0, a1 = 0, a2 = 0, a3 = 0;
        const ulonglong2* wp = Wp0;

#pragma unroll
        for (int it = 0; it < ITS; ++it) {
            float4 s = buf[it];
#pragma unroll
            for (int kk = 0; kk < 4; ++kk) {
                unsigned sb = __float_as_uint(kk == 0 ? s.x : kk == 1 ? s.y
                                                         : kk == 2 ? s.z : s.w);
                unsigned long long svv;
                asm("mov.b64 %0, {%1, %1};" : "=l"(svv) : "r"(sb));
                ulonglong2 u0 = wp[0];
                ulonglong2 u1 = wp[1];
                wp += 2;
                asm("fma.rn.f32x2 %0, %1, %2, %0;" : "+l"(a0) : "l"(svv), "l"(u0.x));
                asm("fma.rn.f32x2 %0, %1, %2, %0;" : "+l"(a1) : "l"(svv), "l"(u0.y));
                asm("fma.rn.f32x2 %0, %1, %2, %0;" : "+l"(a2) : "l"(svv), "l"(u1.x));
                asm("fma.rn.f32x2 %0, %1, %2, %0;" : "+l"(a3) : "l"(svv), "l"(u1.y));
            }
        }

        // ---- stage x(:, t+1, :) for next step (consumed after sync1) ----
        if (t + 1 < Tq) {
#pragma unroll
            for (int l = 0; l < 2; ++l) {
                int idx = tid + l * 512;
                int b = idx >> 5, d4 = idx & 31;
                float4 v = x4[((size_t)b * Tq + (t + 1)) * 32 + d4];
                *(float4*)&sm->xs_x[p ^ 1][b][d4 * 4] = v;
            }
        }

        sm->red[warp][lane][0] = __uint_as_float((unsigned)a0);
        sm->red[warp][lane][1] = __uint_as_float((unsigned)(a0 >> 32));
        sm->red[warp][lane][2] = __uint_as_float((unsigned)a1);
        sm->red[warp][lane][3] = __uint_as_float((unsigned)(a1 >> 32));
        sm->red[warp][lane][4] = __uint_as_float((unsigned)a2);
        sm->red[warp][lane][5] = __uint_as_float((unsigned)(a2 >> 32));
        sm->red[warp][lane][6] = __uint_as_float((unsigned)a3);
        sm->red[warp][lane][7] = __uint_as_float((unsigned)(a3 >> 32));
        __syncthreads();   // sync1: red + xr2 + xs_x(t+1) all visible

        if (epi) {
            float xin = sm->xr2[0][tid] + sm->xr2[1][tid];
            float sum = 0.f;
#pragma unroll
            for (int w = 0; w < NW; ++w) sum += sm->red[w][eb][ec];

            float post = tanhf(sum + xin) + nz;
            outp[(size_t)t * Nq] = post;        // only our own element — safe
            *((t & 1) ? sW1 : sW0) = post;      // next-step state (read via __ldcg)
        }

        // ---- arrive at own group counter (release publishes state writes) ----
        __syncthreads();   // sync2: epilogue reads done; state writes done; HB to t0
        if (tid == 0) {
            asm volatile("red.release.gpu.add.u32 [%0], %1;"
                         :: "l"(own_cnt), "r"(1u) : "memory");
        }
    }
}

extern "C" void kernel_launch(void* const* d_in, const int* in_sizes, int n_in,
                              void* d_out, int out_size) {
    (void)in_sizes; (void)n_in; (void)out_size;
    const float* x       = (const float*)d_in[0];
    const float* w_input = (const float*)d_in[1];
    const float* w_res   = (const float*)d_in[2];
    const float* w_scale = (const float*)d_in[3];
    const float* states0 = (const float*)d_in[4];
    const float* step0   = (const float*)d_in[5];
    const float* rnoise  = (const float*)d_in[6];
    float* out = (float*)d_out;

    cudaFuncSetAttribute(recur_kernel, cudaFuncAttributeMaxDynamicSharedMemorySize,
                         RECUR_SMEM_BYTES);

    init_kernel<<<128, 256>>>(states0, step0, out);
    recur_kernel<<<GRID_G, NTHR, RECUR_SMEM_BYTES>>>(w_res, x, w_input, w_scale,
                                                     rnoise, out);
}

// round 13
// speedup vs baseline: 1.5095x; 1.1562x over previous
#include <cuda_runtime.h>

#define Bq 32
#define Tq 512
#define Dq 128
#define Nq 1024
#define NOISE_C 0.001f
#define GRID_G 128
#define NCOL 8
#define NTHR 512
#define NW 16          // warps per CTA
#define NGRP 16        // producer groups / chunks
#define GSZ 8          // CTAs per group

typedef unsigned long long ull;

// States double buffer, k-major: g_St[ph][k][b] — one 128B line per k.
__device__ float g_St[2][Nq][Bq];
// 16 group counters, one 128B line each. Group g = CTAs [8g,8g+8) = k chunk [64g,64g+64).
// Monotonic; reset by init_kernel each launch -> replay-safe.
__device__ unsigned g_gcnt[NGRP * 32];

// out[:,0,:] = step0 ; pack states0 into g_St[0] ; reset counters
__global__ void init_kernel(const float* __restrict__ states0,
                            const float* __restrict__ step0,
                            float* __restrict__ out) {
    int i = blockIdx.x * blockDim.x + threadIdx.x;  // 0 .. 32767
    int b = i >> 10;
    int n = i & 1023;
    out[(size_t)b * Tq * Nq + n] = step0[i];
    g_St[0][n][b] = states0[i];
    if (i < NGRP * 32) g_gcnt[i] = 0u;
}

struct RecurSmem {
    float Wv[16][64][8];       // 32 KB  W_res slice, k-interleaved: [k%16][k/16][col]
    float red[NW][Bq][12];     // 24 KB  48B rows (pad) for low-conflict STS
    float xs_x[2][Bq][132];    // 33.8 KB  x tile, parity double-buffered
    float wt[NCOL][132];       // 4.2 KB  w_input slice (pre-scaled, transposed)
    float xr2[2][256];         // 2 KB  xin half-dot partials
};
#define RECUR_SMEM_BYTES ((int)sizeof(RecurSmem))

// Persistent recurrence, fused input projection, wavefront-optimized W reads.
// 128 CTAs x 512 threads. Warp w owns k chunk [64w,64w+64); lane = (kq, bg):
// kq = k-quarter (16 k), bg = batch group (4 batches). Each lane: acc[4b][8c]
// over 16 k, W via 4-distinct-address LDS (1 wf), states via 4-full-line LDG.
// Cross-kq reduce: 2 shfl butterflies with packed f32x2 adds.
__global__ __launch_bounds__(NTHR, 1) void recur_kernel(const float* __restrict__ w_res,
                                                        const float* __restrict__ x,
                                                        const float* __restrict__ w_in,
                                                        const float* __restrict__ scale_p,
                                                        const float* __restrict__ noise,
                                                        float* __restrict__ out) {
    extern __shared__ RecurSmem sm[];
    const float4* x4 = (const float4*)x;

    const int tid = threadIdx.x;
    const int cta = blockIdx.x;
    const int col0 = cta * NCOL;
    unsigned* own_cnt = &g_gcnt[(cta >> 3) * 32];   // our group's counter

    // W_res slice, k-interleaved: Wv[k%16][k/16][c] = w_res[k][col0+c]
    for (int i = tid; i < 16 * 64 * 8; i += NTHR) {
        int c = i & 7, g = (i >> 3) & 63, j = i >> 9;
        int k = g * 16 + j;
        sm->Wv[j][g][c] = w_res[(size_t)k * Nq + col0 + c];
    }
    // w_input slice, transposed + pre-scaled
    const float sc = *scale_p;
    for (int i = tid; i < Dq * NCOL; i += NTHR) {
        int d = i >> 3, c = i & 7;
        sm->wt[c][d] = w_in[(size_t)d * Nq + col0 + c] * sc;
    }
    // stage x(:, t=1, :) into parity buffer 1
#pragma unroll
    for (int l = 0; l < 2; ++l) {
        int idx = tid + l * 512;
        int b = idx >> 5, d4 = idx & 31;
        float4 v = x4[((size_t)b * Tq + 1) * 32 + d4];
        *(float4*)&sm->xs_x[1][b][d4 * 4] = v;
    }
    __syncthreads();

    const int warp = tid >> 5;
    const int lane = tid & 31;
    const int kq = lane >> 3;     // k-quarter within warp chunk
    const int bg = lane & 7;      // batch group (4 batches)
    unsigned* my_chunk_cnt = &g_gcnt[warp * 32];

    // epilogue mapping (first 256 threads): thread -> (eb, ec)
    const bool epi = (tid < Bq * NCOL);
    const int eb = (tid >> 3) & 31;
    const int ec = tid & 7;
    const int en = col0 + ec;
    const float nz = epi ? NOISE_C * noise[eb * Nq + en] : 0.f;
    float* outp = out + (size_t)eb * Tq * Nq + en;
    float* sSt0 = &g_St[0][en][eb];
    float* sSt1 = &g_St[1][en][eb];

    // fused-xin half-dot mapping (all 512 threads)
    const int he = tid & 255;
    const int hh = tid >> 8;
    const int heb = (he >> 3) & 31;
    const int hec = he & 7;

    // W base for this lane: ulonglong2 index (j*64 + warp*4 + kq)*2, j-step = 128
    const ulonglong2* Wb = (const ulonglong2*)sm->Wv + (warp * 4 + kq) * 2;
    // state base: float4 index k*8 + bg, k = warp*64 + kq*16
    const int ks0 = (warp * 64 + kq * 16) * 8 + bg;

    for (int t = 1; t < Tq; ++t) {
        const int p = t & 1;

        // ---- fused xin: half-dot over d in [64*hh, 64*hh+64) (gate-independent) ----
        {
            const float4* xp = (const float4*)&sm->xs_x[p][heb][hh * 64];
            const float4* wp4 = (const float4*)&sm->wt[hec][hh * 64];
            ull acc2 = 0;
#pragma unroll
            for (int j = 0; j < 16; ++j) {
                float4 xv = xp[j];
                float4 wv = wp4[j];
                ull x01 = ((const ull*)&xv)[0], x23 = ((const ull*)&xv)[1];
                ull w01 = ((const ull*)&wv)[0], w23 = ((const ull*)&wv)[1];
                asm("fma.rn.f32x2 %0, %1, %2, %0;" : "+l"(acc2) : "l"(x01), "l"(w01));
                asm("fma.rn.f32x2 %0, %1, %2, %0;" : "+l"(acc2) : "l"(x23), "l"(w23));
            }
            sm->xr2[hh][he] = __uint_as_float((unsigned)acc2) +
                              __uint_as_float((unsigned)(acc2 >> 32));
        }

        // ---- per-warp gate: wait for OUR chunk's producers (prev step) ----
        const unsigned tgt = (unsigned)GSZ * (unsigned)(t - 1);
        if (lane == 0) {
            unsigned v;
            do {
                asm volatile("ld.acquire.gpu.u32 %0, [%1];"
                             : "=r"(v) : "l"(my_chunk_cnt) : "memory");
                if (v < tgt) __nanosleep(8);
            } while (v < tgt);
        }
        __syncwarp();

        // ---- main FMA: 16 k steps, acc[4 batches][8 cols] as 16 f32x2 ----
        const float4* Sp = (const float4*)g_St[(t - 1) & 1] + ks0;
        float4 buf[8];
#pragma unroll
        for (int j = 0; j < 8; ++j) buf[j] = __ldcg(Sp + j * 8);

        ull a[16];
#pragma unroll
        for (int m = 0; m < 16; ++m) a[m] = 0ull;

        const ulonglong2* wp = Wb;
#pragma unroll
        for (int j = 0; j < 16; ++j) {
            float4 s = buf[j & 7];                    // 4 batches at k
            if (j < 8) buf[j & 7] = __ldcg(Sp + (j + 8) * 8);
            ulonglong2 u0 = wp[0];                    // cols 0-3 (2 f32x2)
            ulonglong2 u1 = wp[1];                    // cols 4-7
            wp += 128;                                // next j row
            ull sv0, sv1, sv2, sv3;
            asm("mov.b64 %0, {%1, %1};" : "=l"(sv0) : "r"(__float_as_uint(s.x)));
            asm("mov.b64 %0, {%1, %1};" : "=l"(sv1) : "r"(__float_as_uint(s.y)));
            asm("mov.b64 %0, {%1, %1};" : "=l"(sv2) : "r"(__float_as_uint(s.z)));
            asm("mov.b64 %0, {%1, %1};" : "=l"(sv3) : "r"(__float_as_uint(s.w)));
            asm("fma.rn.f32x2 %0, %1, %2, %0;" : "+l"(a[0])  : "l"(sv0), "l"(u0.x));
            asm("fma.rn.f32x2 %0, %1, %2, %0;" : "+l"(a[1])  : "l"(sv0), "l"(u0.y));
            asm("fma.rn.f32x2 %0, %1, %2, %0;" : "+l"(a[2])  : "l"(sv0), "l"(u1.x));
            asm("fma.rn.f32x2 %0, %1, %2, %0;" : "+l"(a[3])  : "l"(sv0), "l"(u1.y));
            asm("fma.rn.f32x2 %0, %1, %2, %0;" : "+l"(a[4])  : "l"(sv1), "l"(u0.x));
            asm("fma.rn.f32x2 %0, %1, %2, %0;" : "+l"(a[5])  : "l"(sv1), "l"(u0.y));
            asm("fma.rn.f32x2 %0, %1, %2, %0;" : "+l"(a[6])  : "l"(sv1), "l"(u1.x));
            asm("fma.rn.f32x2 %0, %1, %2, %0;" : "+l"(a[7])  : "l"(sv1), "l"(u1.y));
            asm("fma.rn.f32x2 %0, %1, %2, %0;" : "+l"(a[8])  : "l"(sv2), "l"(u0.x));
            asm("fma.rn.f32x2 %0, %1, %2, %0;" : "+l"(a[9])  : "l"(sv2), "l"(u0.y));
            asm("fma.rn.f32x2 %0, %1, %2, %0;" : "+l"(a[10]) : "l"(sv2), "l"(u1.x));
            asm("fma.rn.f32x2 %0, %1, %2, %0;" : "+l"(a[11]) : "l"(sv2), "l"(u1.y));
            asm("fma.rn.f32x2 %0, %1, %2, %0;" : "+l"(a[12]) : "l"(sv3), "l"(u0.x));
            asm("fma.rn.f32x2 %0, %1, %2, %0;" : "+l"(a[13]) : "l"(sv3), "l"(u0.y));
            asm("fma.rn.f32x2 %0, %1, %2, %0;" : "+l"(a[14]) : "l"(sv3), "l"(u1.x));
            asm("fma.rn.f32x2 %0, %1, %2, %0;" : "+l"(a[15]) : "l"(sv3), "l"(u1.y));
        }

        // ---- cross-kq butterfly (lanes ±8, ±16), packed f32x2 adds ----
#pragma unroll
        for (int m = 0; m < 16; ++m) {
            ull o = __shfl_xor_sync(0xffffffffu, a[m], 8);
            asm("add.rn.f32x2 %0, %0, %1;" : "+l"(a[m]) : "l"(o));
        }
#pragma unroll
        for (int m = 0; m < 16; ++m) {
            ull o = __shfl_xor_sync(0xffffffffu, a[m], 16);
            asm("add.rn.f32x2 %0, %0, %1;" : "+l"(a[m]) : "l"(o));
        }

        // ---- stage x(:, t+1, :) for next step (consumed after sync1) ----
        if (t + 1 < Tq) {
#pragma unroll
            for (int l = 0; l < 2; ++l) {
                int idx = tid + l * 512;
                int b = idx >> 5, d4 = idx & 31;
                float4 v = x4[((size_t)b * Tq + (t + 1)) * 32 + d4];
                *(float4*)&sm->xs_x[p ^ 1][b][d4 * 4] = v;
            }
        }

        if (kq == 0) {   // lanes 0-7 hold full warp-chunk sums for (4b x 8c)
#pragma unroll
            for (int i = 0; i < 4; ++i) {
                ull2_store: ;
                *(ulonglong2*)&sm->red[warp][bg * 4 + i][0] =
                    make_ulonglong2(a[i * 4 + 0], a[i * 4 + 1]);
                *(ulonglong2*)&sm->red[warp][bg * 4 + i][4] =
                    make_ulonglong2(a[i * 4 + 2], a[i * 4 + 3]);
            }
        }
        __syncthreads();   // sync1: red + xr2 + xs_x(t+1) all visible

        if (epi) {
            float xin = sm->xr2[0][tid] + sm->xr2[1][tid];
            float sum = 0.f;
#pragma unroll
            for (int w = 0; w < NW; ++w) sum += sm->red[w][eb][ec];

            float post = tanhf(sum + xin) + nz;
            outp[(size_t)t * Nq] = post;        // only our own element — safe
            *((p) ? sSt1 : sSt0) = post;        // next-step state (read via __ldcg)
        }

        // ---- arrive at own group counter (release publishes state writes) ----
        __syncthreads();   // sync2: epilogue reads done; state writes done; HB to t0
        if (tid == 0) {
            asm volatile("red.release.gpu.add.u32 [%0], %1;"
                         :: "l"(own_cnt), "r"(1u) : "memory");
        }
    }
}

extern "C" void kernel_launch(void* const* d_in, const int* in_sizes, int n_in,
                              void* d_out, int out_size) {
    (void)in_sizes; (void)n_in; (void)out_size;
    const float* x       = (const float*)d_in[0];
    const float* w_input = (const float*)d_in[1];
    const float* w_res   = (const float*)d_in[2];
    const float* w_scale = (const float*)d_in[3];
    const float* states0 = (const float*)d_in[4];
    const float* step0   = (const float*)d_in[5];
    const float* rnoise  = (const float*)d_in[6];
    float* out = (float*)d_out;

    cudaFuncSetAttribute(recur_kernel, cudaFuncAttributeMaxDynamicSharedMemorySize,
                         RECUR_SMEM_BYTES);

    init_kernel<<<128, 256>>>(states0, step0, out);
    recur_kernel<<<GRID_G, NTHR, RECUR_SMEM_BYTES>>>(w_res, x, w_input, w_scale,
                                                     rnoise, out);
}

// round 14
// speedup vs baseline: 1.5848x; 1.0499x over previous
#include <cuda_runtime.h>

#define Bq 32
#define Tq 512
#define Dq 128
#define Nq 1024
#define NOISE_C 0.001f
#define GRID_G 128
#define NBL 16         // batches per CTA
#define NCOL 16        // cols per CTA
#define NTHR 512
#define NW 16          // warps per CTA

typedef unsigned long long ull;

// States double buffer: g_Sg[ph][bg][k][16] — 64B per k, warp reads 2 full lines/instr.
__device__ float g_Sg[2][2][Nq][NBL];
// Counters g_gc[bg][w][32]: chunk w of batch-group bg; 4 producer CTAs each.
// Monotonic; reset by init_kernel each launch -> replay-safe.
__device__ unsigned g_gc[2 * 16 * 32];

// out[:,0,:] = step0 ; pack states0 ; reset counters
__global__ void init_kernel(const float* __restrict__ states0,
                            const float* __restrict__ step0,
                            float* __restrict__ out) {
    int i = blockIdx.x * blockDim.x + threadIdx.x;  // 0 .. 32767
    int b = i >> 10;
    int n = i & 1023;
    out[(size_t)b * Tq * Nq + n] = step0[i];
    g_Sg[0][b >> 4][n][b & 15] = states0[i];
    if (i < 2 * 16 * 32) g_gc[i] = 0u;
}

struct RecurSmem {
    float Wv[NW][16][4][NCOL];   // 64 KB  [w][j][kq][c], k = 64w+4j+kq
    float red[NW][NBL][20];      // 20.5 KB  80B rows (16B-aligned, low-conflict)
    float xs_x[2][NBL][132];     // 16.9 KB  x tile, parity double-buffered
    float wt[NCOL][132];         // 8.4 KB  w_input slice (pre-scaled, transposed)
    float xr2[2][256];           // 2 KB   xin half-dot partials
};
#define RECUR_SMEM_BYTES ((int)sizeof(RecurSmem))

// Persistent recurrence, square 16x16 CTA tiles (balanced LDG/LDS ports),
// fused input projection, per-warp dataflow gating (4-CTA gangs).
// 128 CTAs = 2 bg x 64 cg, 512 threads. Warp w: k chunk [64w,64w+64).
// Lane (kq,bh,ch): 16k x 4b x 8c, acc = 16 f32x2; butterfly over kq.
__global__ __launch_bounds__(NTHR, 1) void recur_kernel(const float* __restrict__ w_res,
                                                        const float* __restrict__ x,
                                                        const float* __restrict__ w_in,
                                                        const float* __restrict__ scale_p,
                                                        const float* __restrict__ noise,
                                                        float* __restrict__ out) {
    extern __shared__ RecurSmem sm[];
    const float4* x4 = (const float4*)x;

    const int tid = threadIdx.x;
    const int cta = blockIdx.x;
    const int bg = cta >> 6;          // 0..1
    const int cg = cta & 63;          // 0..63
    const int col0 = cg * NCOL;
    unsigned* own_cnt = &g_gc[(bg * 16 + (cg >> 2)) * 32];

    // W slice, k-interleaved: Wv[w][j][kq][c] = w_res[64w+4j+kq][col0+c]
    for (int i = tid; i < Nq * NCOL; i += NTHR) {
        int k = i >> 4, c = i & 15;
        sm->Wv[k >> 6][(k >> 2) & 15][k & 3][c] = w_res[(size_t)k * Nq + col0 + c];
    }
    // w_input slice, transposed + pre-scaled
    const float sc = *scale_p;
    for (int i = tid; i < Dq * NCOL; i += NTHR) {
        int d = i >> 4, c = i & 15;
        sm->wt[c][d] = w_in[(size_t)d * Nq + col0 + c] * sc;
    }
    // stage x(:, t=1, :) into parity buffer 1 (16 batches x 32 float4 = 512)
    {
        int b = tid >> 5, d4 = tid & 31;
        float4 v = x4[((size_t)(bg * NBL + b) * Tq + 1) * 32 + d4];
        *(float4*)&sm->xs_x[1][b][d4 * 4] = v;
    }
    __syncthreads();

    const int warp = tid >> 5;
    const int lane = tid & 31;
    const int kq = lane >> 3;         // bits 3,4 -> butterfly xor 8,16
    const int bh = (lane >> 1) & 3;   // 4-batch group
    const int ch = lane & 1;          // 8-col half
    unsigned* my_cnt = &g_gc[(bg * 16 + warp) * 32];

    // epilogue mapping (first 256 threads): eb = tid&15, ec = tid>>4
    const bool epi = (tid < NBL * NCOL);
    const int eb = tid & 15;
    const int ec = (tid >> 4) & 15;
    const int gb = bg * NBL + eb;
    const int gc = col0 + ec;
    const float nz = NOISE_C * noise[gb * Nq + gc];
    float* outp = out + (size_t)gb * Tq * Nq + gc;
    float* sSt0 = &g_Sg[0][bg][gc][eb];
    float* sSt1 = &g_Sg[1][bg][gc][eb];

    // fused-xin half-dot mapping (all 512 threads): he=(heb,hec), hh = d-half
    const int he = tid & 255;
    const int hh = tid >> 8;
    const int heb = he & 15;
    const int hec = (he >> 4) & 15;

    // W base: &Wv[warp][0][kq][ch*8]; j stride = 64 floats = 16 ulonglong2
    const ulonglong2* Wb = (const ulonglong2*)&sm->Wv[warp][0][kq][ch * 8];
    // state float4 base index into g_Sg[ph][bg]: (64*warp+kq)*4 + bh; j stride 16
    const int ks0 = (warp * 64 + kq) * 4 + bh;

    for (int t = 1; t < Tq; ++t) {
        const int p = t & 1;

        // ---- fused xin: half-dot over d in [64*hh, 64*hh+64) (gate-independent) ----
        {
            const float4* xp = (const float4*)&sm->xs_x[p][heb][hh * 64];
            const float4* wp4 = (const float4*)&sm->wt[hec][hh * 64];
            ull acc2 = 0;
#pragma unroll
            for (int j = 0; j < 16; ++j) {
                float4 xv = xp[j];
                float4 wv = wp4[j];
                ull x01 = ((const ull*)&xv)[0], x23 = ((const ull*)&xv)[1];
                ull w01 = ((const ull*)&wv)[0], w23 = ((const ull*)&wv)[1];
                asm("fma.rn.f32x2 %0, %1, %2, %0;" : "+l"(acc2) : "l"(x01), "l"(w01));
                asm("fma.rn.f32x2 %0, %1, %2, %0;" : "+l"(acc2) : "l"(x23), "l"(w23));
            }
            sm->xr2[hh][he] = __uint_as_float((unsigned)acc2) +
                              __uint_as_float((unsigned)(acc2 >> 32));
        }

        // ---- per-warp gate: wait for OUR chunk's 4 producers (prev step) ----
        const unsigned tgt = 4u * (unsigned)(t - 1);
        if (lane == 0) {
            unsigned v;
            do {
                asm volatile("ld.acquire.gpu.u32 %0, [%1];"
                             : "=r"(v) : "l"(my_cnt) : "memory");
                if (v < tgt) __nanosleep(8);
            } while (v < tgt);
        }
        __syncwarp();

        // ---- main FMA: 16 k steps, acc[4b][8c] as 16 f32x2 ----
        const float4* Sp = (const float4*)g_Sg[(t - 1) & 1][bg] + ks0;
        float4 buf[8];
#pragma unroll
        for (int j = 0; j < 8; ++j) buf[j] = __ldcg(Sp + j * 16);

        ull a[16];
#pragma unroll
        for (int m = 0; m < 16; ++m) a[m] = 0ull;

        const ulonglong2* wp = Wb;
#pragma unroll
        for (int j = 0; j < 16; ++j) {
            float4 s = buf[j & 7];                    // 4 batches at k = 64w+4j+kq
            if (j < 8) buf[j & 7] = __ldcg(Sp + (j + 8) * 16);
            ulonglong2 u0 = wp[0];                    // cols ch*8+0..3
            ulonglong2 u1 = wp[1];                    // cols ch*8+4..7
            wp += 16;                                 // next j (64 floats)
            ull sv0, sv1, sv2, sv3;
            asm("mov.b64 %0, {%1, %1};" : "=l"(sv0) : "r"(__float_as_uint(s.x)));
            asm("mov.b64 %0, {%1, %1};" : "=l"(sv1) : "r"(__float_as_uint(s.y)));
            asm("mov.b64 %0, {%1, %1};" : "=l"(sv2) : "r"(__float_as_uint(s.z)));
            asm("mov.b64 %0, {%1, %1};" : "=l"(sv3) : "r"(__float_as_uint(s.w)));
            asm("fma.rn.f32x2 %0, %1, %2, %0;" : "+l"(a[0])  : "l"(sv0), "l"(u0.x));
            asm("fma.rn.f32x2 %0, %1, %2, %0;" : "+l"(a[1])  : "l"(sv0), "l"(u0.y));
            asm("fma.rn.f32x2 %0, %1, %2, %0;" : "+l"(a[2])  : "l"(sv0), "l"(u1.x));
            asm("fma.rn.f32x2 %0, %1, %2, %0;" : "+l"(a[3])  : "l"(sv0), "l"(u1.y));
            asm("fma.rn.f32x2 %0, %1, %2, %0;" : "+l"(a[4])  : "l"(sv1), "l"(u0.x));
            asm("fma.rn.f32x2 %0, %1, %2, %0;" : "+l"(a[5])  : "l"(sv1), "l"(u0.y));
            asm("fma.rn.f32x2 %0, %1, %2, %0;" : "+l"(a[6])  : "l"(sv1), "l"(u1.x));
            asm("fma.rn.f32x2 %0, %1, %2, %0;" : "+l"(a[7])  : "l"(sv1), "l"(u1.y));
            asm("fma.rn.f32x2 %0, %1, %2, %0;" : "+l"(a[8])  : "l"(sv2), "l"(u0.x));
            asm("fma.rn.f32x2 %0, %1, %2, %0;" : "+l"(a[9])  : "l"(sv2), "l"(u0.y));
            asm("fma.rn.f32x2 %0, %1, %2, %0;" : "+l"(a[10]) : "l"(sv2), "l"(u1.x));
            asm("fma.rn.f32x2 %0, %1, %2, %0;" : "+l"(a[11]) : "l"(sv2), "l"(u1.y));
            asm("fma.rn.f32x2 %0, %1, %2, %0;" : "+l"(a[12]) : "l"(sv3), "l"(u0.x));
            asm("fma.rn.f32x2 %0, %1, %2, %0;" : "+l"(a[13]) : "l"(sv3), "l"(u0.y));
            asm("fma.rn.f32x2 %0, %1, %2, %0;" : "+l"(a[14]) : "l"(sv3), "l"(u1.x));
            asm("fma.rn.f32x2 %0, %1, %2, %0;" : "+l"(a[15]) : "l"(sv3), "l"(u1.y));
        }

        // ---- cross-kq butterfly (lanes ±8, ±16), packed f32x2 adds ----
#pragma unroll
        for (int m = 0; m < 16; ++m) {
            ull o = __shfl_xor_sync(0xffffffffu, a[m], 8);
            asm("add.rn.f32x2 %0, %0, %1;" : "+l"(a[m]) : "l"(o));
        }
#pragma unroll
        for (int m = 0; m < 16; ++m) {
            ull o = __shfl_xor_sync(0xffffffffu, a[m], 16);
            asm("add.rn.f32x2 %0, %0, %1;" : "+l"(a[m]) : "l"(o));
        }

        // ---- stage x(:, t+1, :) for next step (consumed after sync1) ----
        if (t + 1 < Tq) {
            int b = tid >> 5, d4 = tid & 31;
            float4 v = x4[((size_t)(bg * NBL + b) * Tq + (t + 1)) * 32 + d4];
            *(float4*)&sm->xs_x[p ^ 1][b][d4 * 4] = v;
        }

        if (kq == 0) {   // lanes 0-7 (bh,ch) hold warp-chunk sums for (4b x 8c)
#pragma unroll
            for (int i = 0; i < 4; ++i) {
                *(ulonglong2*)&sm->red[warp][bh * 4 + i][ch * 8] =
                    make_ulonglong2(a[i * 4 + 0], a[i * 4 + 1]);
                *(ulonglong2*)&sm->red[warp][bh * 4 + i][ch * 8 + 4] =
                    make_ulonglong2(a[i * 4 + 2], a[i * 4 + 3]);
            }
        }
        __syncthreads();   // sync1: red + xr2 + xs_x(t+1) all visible

        if (epi) {
            float xin = sm->xr2[0][tid] + sm->xr2[1][tid];
            float sum = 0.f;
#pragma unroll
            for (int w = 0; w < NW; ++w) sum += sm->red[w][eb][ec];

            float post = tanhf(sum + xin) + nz;
            outp[(size_t)t * Nq] = post;        // only our own element — safe
            *((p) ? sSt1 : sSt0) = post;        // next-step state (read via __ldcg)
        }

        // ---- arrive at own gang counter (release publishes state writes) ----
        __syncthreads();   // sync2: epilogue reads done; state writes done; HB to t0
        if (tid == 0) {
            asm volatile("red.release.gpu.add.u32 [%0], %1;"
                         :: "l"(own_cnt), "r"(1u) : "memory");
        }
    }
}

extern "C" void kernel_launch(void* const* d_in, const int* in_sizes, int n_in,
                              void* d_out, int out_size) {
    (void)in_sizes; (void)n_in; (void)out_size;
    const float* x       = (const float*)d_in[0];
    const float* w_input = (const float*)d_in[1];
    const float* w_res   = (const float*)d_in[2];
    const float* w_scale = (const float*)d_in[3];
    const float* states0 = (const float*)d_in[4];
    const float* step0   = (const float*)d_in[5];
    const float* rnoise  = (const float*)d_in[6];
    float* out = (float*)d_out;

    cudaFuncSetAttribute(recur_kernel, cudaFuncAttributeMaxDynamicSharedMemorySize,
                         RECUR_SMEM_BYTES);

    init_kernel<<<128, 256>>>(states0, step0, out);
    recur_kernel<<<GRID_G, NTHR, RECUR_SMEM_BYTES>>>(w_res, x, w_input, w_scale,
                                                     rnoise, out);
}